// round 14
// baseline (speedup 1.0000x reference)
#include <cuda_runtime.h>
#include <cuda_bf16.h>
#include <math.h>
#include <stdint.h>

#define B_ 8
#define L_ 1024
#define H_ 1024
#define N_ 32
#define NL_ 4
#define TOK_ (B_ * L_)        // 8192 tokens
#define BH_ (B_ / 2)          // batches per chain
#define TOKH_ (TOK_ / 2)      // tokens per chain

// fp8 correction scales: S_A*S_WLO == S_ALO*S_W == 2^18
#define S_A_   8.0f
#define S_WLO_ 32768.0f
#define S_ALO_ 512.0f
#define S_W_   512.0f
#define INV_CORR_ (1.0f / 262144.0f)

// ---------------- scratch (static device globals) -----------------------------------
__device__ float g_h[(size_t)TOK_ * H_];            // residual, token-major (B*L, H)
__device__ float g_z[(size_t)B_ * H_ * L_];         // post-LN, (B,H,L) for scan
__device__ float g_y[(size_t)B_ * H_ * L_];         // post scan+gelu, (B,H,L)
__device__ __nv_bfloat16 g_ahi[(size_t)TOK_ * H_];  // scan out, token-major bf16 hi
__device__ uint8_t g_af8[(size_t)TOK_ * H_];        // A * 8   in e4m3
__device__ uint8_t g_alo8[(size_t)TOK_ * H_];       // (A-Ahi) * 512 in e4m3
__device__ __nv_bfloat16 g_whi[(size_t)NL_ * 2 * H_ * H_];  // interleaved W, bf16 hi
__device__ uint8_t g_w8[(size_t)NL_ * 2 * H_ * H_];         // W * 512 in e4m3
__device__ uint8_t g_wlo8[(size_t)NL_ * 2 * H_ * H_];       // (W-Whi) * 32768 in e4m3
__device__ float g_biasr[NL_ * 2 * H_];             // interleaved bias
__device__ float g_mu[TOK_];
__device__ float g_rs[TOK_];
__device__ float g_lam_re[NL_ * H_ * N_];
__device__ float g_lam_im[NL_ * H_ * N_];
__device__ float g_cp_re[NL_ * H_ * N_];
__device__ float g_cp_im[NL_ * H_ * N_];

// ---------------- PTX helpers (sm_80/89 generic only; NO 'a'-features) ---------------
__device__ __forceinline__ uint32_t smem_u32(const void* p) {
    uint32_t a;
    asm("{ .reg .u64 t; cvta.to.shared.u64 t, %1; cvt.u32.u64 %0, t; }" : "=r"(a) : "l"(p));
    return a;
}
__device__ __forceinline__ void cp16(uint32_t s, const void* g) {
    asm volatile("cp.async.cg.shared.global [%0], [%1], 16;" :: "r"(s), "l"(g));
}
__device__ __forceinline__ void cp_commit() {
    asm volatile("cp.async.commit_group;" ::: "memory");
}
__device__ __forceinline__ void cp_wait1() {
    asm volatile("cp.async.wait_group 1;" ::: "memory");
}
#define SWZ(off) ((off) ^ (((off) >> 3) & 0x70))

__device__ __forceinline__ void ldmx4(uint32_t* r, uint32_t addr) {
    asm volatile("ldmatrix.sync.aligned.m8n8.x4.shared.b16 {%0,%1,%2,%3}, [%4];"
                 : "=r"(r[0]), "=r"(r[1]), "=r"(r[2]), "=r"(r[3]) : "r"(addr));
}
__device__ __forceinline__ void mma16816(float* c, const uint32_t* a, uint32_t b0, uint32_t b1) {
    asm volatile(
        "mma.sync.aligned.m16n8k16.row.col.f32.bf16.bf16.f32 "
        "{%0,%1,%2,%3}, {%4,%5,%6,%7}, {%8,%9}, {%0,%1,%2,%3};"
        : "+f"(c[0]), "+f"(c[1]), "+f"(c[2]), "+f"(c[3])
        : "r"(a[0]), "r"(a[1]), "r"(a[2]), "r"(a[3]), "r"(b0), "r"(b1));
}
// fp8 e4m3 k32 mma (sm_89+ generic)
__device__ __forceinline__ void mma_fp8(float* c, const uint32_t* a, uint32_t b0, uint32_t b1) {
    asm volatile(
        "mma.sync.aligned.m16n8k32.row.col.f32.e4m3.e4m3.f32 "
        "{%0,%1,%2,%3}, {%4,%5,%6,%7}, {%8,%9}, {%0,%1,%2,%3};"
        : "+f"(c[0]), "+f"(c[1]), "+f"(c[2]), "+f"(c[3])
        : "r"(a[0]), "r"(a[1]), "r"(a[2]), "r"(a[3]), "r"(b0), "r"(b1));
}
// pack two floats into e4m3x2 (low byte = first arg 'a')
__device__ __forceinline__ uint16_t q8x2(float a, float b) {
    uint16_t q;
    asm("cvt.rn.satfinite.e4m3x2.f32 %0, %1, %2;" : "=h"(q) : "f"(b), "f"(a));
    return q;
}

// ---------------- precompute lambda / C' (fp64) --------------------------------------
__global__ void precompute_kernel(const float* __restrict__ log_dt,
                                  const float* __restrict__ A_re_log,
                                  const float* __restrict__ A_im,
                                  const float* __restrict__ C_re,
                                  const float* __restrict__ C_im) {
    int idx = blockIdx.x * blockDim.x + threadIdx.x;
    if (idx >= NL_ * H_ * N_) return;
    int lh = idx / N_;
    double dt  = exp((double)log_dt[lh]);
    double Are = -exp((double)A_re_log[idx]);
    double Aim = (double)A_im[idx];
    double dre = Are * dt, dim = Aim * dt;
    double er  = exp(dre);
    double lre = er * cos(dim), lim = er * sin(dim);
    g_lam_re[idx] = (float)lre;
    g_lam_im[idx] = (float)lim;
    double e1re = lre - 1.0, e1im = lim;
    double den  = Are * Are + Aim * Aim;
    double fre  = (e1re * Are + e1im * Aim) / den;
    double fim  = (e1im * Are - e1re * Aim) / den;
    double cr = (double)C_re[idx], ci = (double)C_im[idx];
    g_cp_re[idx] = (float)(cr * fre - ci * fim);
    g_cp_im[idx] = (float)(cr * fim + ci * fre);
}

// ---------------- W reorder + bf16 hi + fp8 (W, Wlo) --------------------------------
// one thread per (layer, n, k-pair)
__global__ void precompute_w_kernel(const float* __restrict__ W_out,
                                    const float* __restrict__ b_out) {
    size_t idx = (size_t)blockIdx.x * blockDim.x + threadIdx.x;
    if (idx >= (size_t)NL_ * 2 * H_ * (H_ / 2)) return;
    int kp = (int)(idx & (H_ / 2 - 1));
    int n  = (int)((idx >> 9) & (2 * H_ - 1));
    int layer = (int)(idx >> 20);
    int o = n >> 1, s = n & 1;
    int src_row = s ? (H_ + o) : o;
    const float* wr = W_out + ((size_t)layer * 2 * H_ + src_row) * H_;
    float v0 = wr[2 * kp], v1 = wr[2 * kp + 1];
    __nv_bfloat16 h0 = __float2bfloat16(v0), h1 = __float2bfloat16(v1);
    float h0f = __bfloat162float(h0), h1f = __bfloat162float(h1);
    size_t dbase = ((size_t)layer * 2 * H_ + n) * H_ + 2 * kp;
    uint32_t pk = (uint32_t)(*(uint16_t*)&h0) | ((uint32_t)(*(uint16_t*)&h1) << 16);
    *(uint32_t*)(g_whi + dbase) = pk;
    *(uint16_t*)(g_w8 + dbase)   = q8x2(v0 * S_W_, v1 * S_W_);
    *(uint16_t*)(g_wlo8 + dbase) = q8x2((v0 - h0f) * S_WLO_, (v1 - h1f) * S_WLO_);
    if (kp == 0) g_biasr[layer * 2 * H_ + n] = b_out[layer * 2 * H_ + src_row];
}

// ---------------- copies --------------------------------------------------------------
__global__ void copy_in_kernel(const float4* __restrict__ src) {
    int i = blockIdx.x * blockDim.x + threadIdx.x;
    ((float4*)g_h)[i] = src[i];
}
__global__ void copy_out_kernel(float4* __restrict__ dst) {
    int i = blockIdx.x * blockDim.x + threadIdx.x;
    dst[i] = ((const float4*)g_h)[i];
}

// ---------------- LN stats: per-token mean / rstd (token-major g_h) ------------------
__global__ void ln_stats_kernel(int tok0) {
    int wid = threadIdx.x >> 5, lane = threadIdx.x & 31;
    int token = tok0 + blockIdx.x * 8 + wid;
    const float4* p = (const float4*)(g_h + (size_t)token * H_);
    float s = 0.f, ss = 0.f;
    #pragma unroll
    for (int j = 0; j < 8; j++) {
        float4 v = p[lane + j * 32];
        s  += v.x + v.y + v.z + v.w;
        ss += v.x * v.x + v.y * v.y + v.z * v.z + v.w * v.w;
    }
    #pragma unroll
    for (int o = 16; o > 0; o >>= 1) {
        s  += __shfl_xor_sync(0xffffffffu, s, o);
        ss += __shfl_xor_sync(0xffffffffu, ss, o);
    }
    if (lane == 0) {
        float mu = s * (1.0f / H_);
        float var = ss * (1.0f / H_) - mu * mu;
        g_mu[token] = mu;
        g_rs[token] = rsqrtf(var + 1e-5f);
    }
}

// ---------------- LN apply + transpose: g_h(token,H) -> g_z(B,H,L) -------------------
__global__ void ln_apply_t_kernel(const float* __restrict__ ln_w,
                                  const float* __restrict__ ln_b, int layer, int b0) {
    __shared__ float tile[32][33];
    int b = b0 + blockIdx.z;
    int h0 = blockIdx.x * 32, l0 = blockIdx.y * 32;
    int tx = threadIdx.x, ty = threadIdx.y;
    float w  = ln_w[layer * H_ + h0 + tx];
    float bb = ln_b[layer * H_ + h0 + tx];
    #pragma unroll
    for (int i = ty; i < 32; i += 8) {
        int token = b * L_ + l0 + i;
        float v = g_h[(size_t)token * H_ + h0 + tx];
        tile[i][tx] = (v - g_mu[token]) * g_rs[token] * w + bb;
    }
    __syncthreads();
    #pragma unroll
    for (int i = ty; i < 32; i += 8)
        g_z[(size_t)b * H_ * L_ + (size_t)(h0 + i) * L_ + l0 + tx] = tile[tx][i];
}

// ---------------- S4D scan + D_skip + gelu (R10 version — verified fast) -------------
__global__ __launch_bounds__(256) void scan_kernel(const float* __restrict__ D_skip,
                                                   int layer, int bh0) {
    __shared__ float red[8][32 * 33];
    int warp = (blockIdx.x * blockDim.x + threadIdx.x) >> 5;
    int wip  = threadIdx.x >> 5;
    int lane = threadIdx.x & 31;
    int bh = bh0 + warp;
    int h  = bh & (H_ - 1);
    int pidx = (layer * H_ + h) * N_ + lane;
    float lr = g_lam_re[pidx], li = g_lam_im[pidx];
    float cr = g_cp_re[pidx],  ci = g_cp_im[pidx];
    float D  = D_skip[layer * H_ + h];
    const float* zp = g_z + (size_t)bh * L_;
    float* yp = g_y + (size_t)bh * L_;
    float* rb = red[wip];
    float sre = 0.f, sim = 0.f;
    for (int l0 = 0; l0 < L_; l0 += 32) {
        const float4* zp4 = (const float4*)(zp + l0);
        float r[32];
        #pragma unroll
        for (int q = 0; q < 8; q++) {
            float4 zv4 = zp4[q];   // uniform address -> broadcast
            float zz[4] = {zv4.x, zv4.y, zv4.z, zv4.w};
            #pragma unroll
            for (int u = 0; u < 4; u++) {
                float z = zz[u];
                float nre = fmaf(lr, sre, fmaf(-li, sim, z));
                float nim = fmaf(li, sre, lr * sim);
                sre = nre; sim = nim;
                r[q * 4 + u] = fmaf(cr, sre, -ci * sim);
            }
        }
        #pragma unroll
        for (int j = 0; j < 32; j++)
            rb[j * 33 + lane] = r[j];
        __syncwarp();
        const float* row = rb + lane * 33;
        float s0 = 0.f, s1 = 0.f, s2 = 0.f, s3 = 0.f;
        #pragma unroll
        for (int n = 0; n < 32; n += 4) {
            s0 += row[n];
            s1 += row[n + 1];
            s2 += row[n + 2];
            s3 += row[n + 3];
        }
        float sum = (s0 + s1) + (s2 + s3);
        __syncwarp();
        float z  = zp[l0 + lane];
        float xv = 2.0f * sum + D * z;
        float u  = 0.7978845608028654f * (xv + 0.044715f * xv * xv * xv);
        float t  = tanhf(u);
        yp[l0 + lane] = 0.5f * xv * (1.0f + t);
    }
}

// ---------------- convert+transpose: g_y(B,H,L) -> ahi bf16 + af8/alo8 e4m3 ----------
__global__ void convert_kernel(int b0) {
    __shared__ float tile[32][33];   // tile[h-idx][l-idx]
    int b = b0 + blockIdx.z;
    int h0 = blockIdx.x * 32, l0 = blockIdx.y * 32;
    int tx = threadIdx.x, ty = threadIdx.y;
    #pragma unroll
    for (int i = ty; i < 32; i += 8)
        tile[i][tx] = g_y[(size_t)b * H_ * L_ + (size_t)(h0 + i) * L_ + l0 + tx];
    __syncthreads();
    int tid = ty * 32 + tx;
    #pragma unroll
    for (int t = tid; t < 512; t += 256) {
        int hp = t & 15, ll = t >> 4;        // hp: h-pair, ll: l index
        float a0 = tile[2 * hp][ll], a1 = tile[2 * hp + 1][ll];
        __nv_bfloat16 h0b = __float2bfloat16(a0), h1b = __float2bfloat16(a1);
        uint32_t pk = (uint32_t)(*(uint16_t*)&h0b) | ((uint32_t)(*(uint16_t*)&h1b) << 16);
        float lo0 = (a0 - __bfloat162float(h0b)) * S_ALO_;
        float lo1 = (a1 - __bfloat162float(h1b)) * S_ALO_;
        size_t base = ((size_t)(b * L_ + l0 + ll)) * H_ + h0 + 2 * hp;
        *(uint32_t*)(g_ahi + base) = pk;
        *(uint16_t*)(g_af8 + base)  = q8x2(a0 * S_A_, a1 * S_A_);
        *(uint16_t*)(g_alo8 + base) = q8x2(lo0, lo1);
    }
}

// ---------------- GEMM: bf16 main + fp8 corrections + fused bias/GLU/residual --------
// CTA 128(m) x 128(n), 256 thr = 8 warps (4m x 2n), warp tile 32x64.
// Per K=64 chunk: main Ahi*Whi via 4x k16 bf16 mma; corrections
// (A*Wlo + Alo*W, both scaled by 2^18) via 2x k32 e4m3 mma into a shared f32 acc.
#define G_KC 64
#define G_NCHUNK 16
#define GSTG 65536u             // per-stage bytes
#define S_AHI  0u               // 128 x 128B bf16
#define S_WHI  16384u           // 128 x 128B bf16
#define S_AF8  32768u           // 128 x 64B fp8 (2 rows per 128B line)
#define S_ALO8 40960u
#define S_W8   49152u
#define S_WLO8 57344u

__device__ __forceinline__ void fetch_chunk(uint32_t base, int c, int m0, int n0,
                                            const __nv_bfloat16* whiL,
                                            const uint8_t* w8L,
                                            const uint8_t* wlo8L, int tid) {
    int k0 = c * G_KC;
    uint32_t st = base + (uint32_t)(c & 1) * GSTG;
    #pragma unroll
    for (int i = 0; i < 4; i++) {          // Ahi: 128 rows x 128B
        int seg = tid + i * 256, row = seg >> 3, sg = seg & 7;
        cp16(st + S_AHI + SWZ(row * 128 + sg * 16),
             g_ahi + (size_t)(m0 + row) * H_ + k0 + sg * 8);
    }
    #pragma unroll
    for (int i = 0; i < 4; i++) {          // Whi: 128 rows x 128B
        int seg = tid + i * 256, row = seg >> 3, sg = seg & 7;
        cp16(st + S_WHI + SWZ(row * 128 + sg * 16),
             whiL + (size_t)(n0 + row) * H_ + k0 + sg * 8);
    }
    #pragma unroll
    for (int i = 0; i < 2; i++) {          // Af8: 128 rows x 64B
        int seg = tid + i * 256, row = seg >> 2, sg = seg & 3;
        uint32_t off = (uint32_t)(row >> 1) * 128 + (uint32_t)(row & 1) * 64 + sg * 16;
        cp16(st + S_AF8 + SWZ(off), g_af8 + (size_t)(m0 + row) * H_ + k0 + sg * 16);
    }
    #pragma unroll
    for (int i = 0; i < 2; i++) {          // Alo8
        int seg = tid + i * 256, row = seg >> 2, sg = seg & 3;
        uint32_t off = (uint32_t)(row >> 1) * 128 + (uint32_t)(row & 1) * 64 + sg * 16;
        cp16(st + S_ALO8 + SWZ(off), g_alo8 + (size_t)(m0 + row) * H_ + k0 + sg * 16);
    }
    #pragma unroll
    for (int i = 0; i < 2; i++) {          // W8: 128 rows x 64B
        int seg = tid + i * 256, row = seg >> 2, sg = seg & 3;
        uint32_t off = (uint32_t)(row >> 1) * 128 + (uint32_t)(row & 1) * 64 + sg * 16;
        cp16(st + S_W8 + SWZ(off), w8L + (size_t)(n0 + row) * H_ + k0 + sg * 16);
    }
    #pragma unroll
    for (int i = 0; i < 2; i++) {          // Wlo8
        int seg = tid + i * 256, row = seg >> 2, sg = seg & 3;
        uint32_t off = (uint32_t)(row >> 1) * 128 + (uint32_t)(row & 1) * 64 + sg * 16;
        cp16(st + S_WLO8 + SWZ(off), wlo8L + (size_t)(n0 + row) * H_ + k0 + sg * 16);
    }
}

__global__ __launch_bounds__(256, 1) void gemm_kernel(int layer, int tok0) {
    extern __shared__ __align__(1024) char dsm[];
    uint32_t base = smem_u32(dsm);
    int tid = threadIdx.x, lane = tid & 31, wid = tid >> 5;
    int warp_m = wid & 3, warp_n = wid >> 2;      // 4m x 2n warps
    int n0 = blockIdx.x * 128;
    int m0 = tok0 + blockIdx.y * 128;

    const __nv_bfloat16* whiL = g_whi + (size_t)layer * 2 * H_ * H_;
    const uint8_t* w8L   = g_w8   + (size_t)layer * 2 * H_ * H_;
    const uint8_t* wlo8L = g_wlo8 + (size_t)layer * 2 * H_ * H_;

    // per-lane ldmatrix constants
    int grp = lane >> 3, idx8 = lane & 7;
    int r8 = (grp & 1) * 8 + idx8;
    uint32_t klane = (uint32_t)(grp >> 1) * 16;   // 0 or 16 bytes
    uint32_t aoff[2], axor[2], a8b[2], a8x[2];
    uint32_t boff[4], bxor[4], b8b[4], b8x[4];
    #pragma unroll
    for (int mt = 0; mt < 2; mt++) {
        int row = warp_m * 32 + mt * 16 + r8;
        aoff[mt] = (uint32_t)row * 128;
        axor[mt] = (uint32_t)(row & 7) << 4;
        a8b[mt]  = ((uint32_t)(row >> 1) << 7) | ((uint32_t)(row & 1) << 6);
        a8x[mt]  = (uint32_t)((row >> 1) & 7) << 4;
    }
    #pragma unroll
    for (int nt2 = 0; nt2 < 4; nt2++) {
        int row = warp_n * 64 + nt2 * 16 + r8;
        boff[nt2] = (uint32_t)row * 128;
        bxor[nt2] = (uint32_t)(row & 7) << 4;
        b8b[nt2]  = ((uint32_t)(row >> 1) << 7) | ((uint32_t)(row & 1) << 6);
        b8x[nt2]  = (uint32_t)((row >> 1) & 7) << 4;
    }

    float acc[2][8][4];    // main (bf16 hi*hi)
    float acc2[2][8][4];   // corrections (scaled by 2^18)
    #pragma unroll
    for (int mt = 0; mt < 2; mt++)
        #pragma unroll
        for (int nt = 0; nt < 8; nt++)
            #pragma unroll
            for (int u = 0; u < 4; u++) { acc[mt][nt][u] = 0.f; acc2[mt][nt][u] = 0.f; }

    fetch_chunk(base, 0, m0, n0, whiL, w8L, wlo8L, tid);
    cp_commit();

    for (int c = 0; c < G_NCHUNK; c++) {
        if (c + 1 < G_NCHUNK) fetch_chunk(base, c + 1, m0, n0, whiL, w8L, wlo8L, tid);
        cp_commit();
        cp_wait1();
        __syncthreads();

        uint32_t stage = base + (uint32_t)(c & 1) * GSTG;
        // ---- main bf16: 4 x k16 ----
        #pragma unroll
        for (int ks = 0; ks < 4; ks++) {
            uint32_t kb = (uint32_t)ks * 32 + klane;
            uint32_t ah[2][4];
            #pragma unroll
            for (int mt = 0; mt < 2; mt++)
                ldmx4(ah[mt], stage + S_AHI + aoff[mt] + (kb ^ axor[mt]));
            uint32_t w[4][4];
            #pragma unroll
            for (int nt2 = 0; nt2 < 4; nt2++)
                ldmx4(w[nt2], stage + S_WHI + boff[nt2] + (kb ^ bxor[nt2]));
            #pragma unroll
            for (int mt = 0; mt < 2; mt++)
                #pragma unroll
                for (int nt2 = 0; nt2 < 4; nt2++) {
                    mma16816(acc[mt][2 * nt2],     ah[mt], w[nt2][0], w[nt2][2]);
                    mma16816(acc[mt][2 * nt2 + 1], ah[mt], w[nt2][1], w[nt2][3]);
                }
        }
        // ---- corrections fp8: 2 x k32, shared scaled accumulator ----
        #pragma unroll
        for (int ks2 = 0; ks2 < 2; ks2++) {
            uint32_t kc = (uint32_t)ks2 * 32 + klane;
            uint32_t af[2][4], al8[2][4];
            #pragma unroll
            for (int mt = 0; mt < 2; mt++) {
                uint32_t o = (a8b[mt] + kc) ^ a8x[mt];
                ldmx4(af[mt],  stage + S_AF8 + o);
                ldmx4(al8[mt], stage + S_ALO8 + o);
            }
            uint32_t w8f[4][4], wl8f[4][4];
            #pragma unroll
            for (int nt2 = 0; nt2 < 4; nt2++) {
                uint32_t o = (b8b[nt2] + kc) ^ b8x[nt2];
                ldmx4(w8f[nt2],  stage + S_W8 + o);
                ldmx4(wl8f[nt2], stage + S_WLO8 + o);
            }
            #pragma unroll
            for (int mt = 0; mt < 2; mt++)
                #pragma unroll
                for (int nt2 = 0; nt2 < 4; nt2++) {
                    mma_fp8(acc2[mt][2 * nt2],     af[mt],  wl8f[nt2][0], wl8f[nt2][2]);
                    mma_fp8(acc2[mt][2 * nt2 + 1], af[mt],  wl8f[nt2][1], wl8f[nt2][3]);
                    mma_fp8(acc2[mt][2 * nt2],     al8[mt], w8f[nt2][0],  w8f[nt2][2]);
                    mma_fp8(acc2[mt][2 * nt2 + 1], al8[mt], w8f[nt2][1],  w8f[nt2][3]);
                }
        }
        __syncthreads();
    }

    // epilogue: bias + GLU (adjacent interleaved col pairs in-thread) + residual
    int g = lane >> 2, tig = lane & 3;
    const float* bp = g_biasr + layer * 2 * H_;
    #pragma unroll
    for (int mt = 0; mt < 2; mt++) {
        int mrow = m0 + warp_m * 32 + mt * 16 + g;
        float* hr0 = g_h + (size_t)mrow * H_;
        float* hr1 = hr0 + (size_t)8 * H_;
        #pragma unroll
        for (int nt = 0; nt < 8; nt++) {
            int ncol = n0 + warp_n * 64 + nt * 8 + 2 * tig;  // even
            float b1v = bp[ncol], b2v = bp[ncol + 1];
            int hcol = ncol >> 1;
            float o1 = acc[mt][nt][0] + acc2[mt][nt][0] * INV_CORR_ + b1v;
            float o2 = acc[mt][nt][1] + acc2[mt][nt][1] * INV_CORR_ + b2v;
            hr0[hcol] += o1 / (1.0f + expf(-o2));
            o1 = acc[mt][nt][2] + acc2[mt][nt][2] * INV_CORR_ + b1v;
            o2 = acc[mt][nt][3] + acc2[mt][nt][3] * INV_CORR_ + b2v;
            hr1[hcol] += o1 / (1.0f + expf(-o2));
        }
    }
}

// ---------------- launch -------------------------------------------------------------
// R10 stream topology (plain fork, two batch-half chains).
extern "C" void kernel_launch(void* const* d_in, const int* in_sizes, int n_in,
                              void* d_out, int out_size) {
    const float* x        = (const float*)d_in[0];
    const float* ln_w     = (const float*)d_in[1];
    const float* ln_b     = (const float*)d_in[2];
    const float* log_dt   = (const float*)d_in[3];
    const float* A_re_log = (const float*)d_in[4];
    const float* A_im     = (const float*)d_in[5];
    const float* C_re     = (const float*)d_in[6];
    const float* C_im     = (const float*)d_in[7];
    const float* D_skip   = (const float*)d_in[8];
    const float* W_out    = (const float*)d_in[9];
    const float* b_out    = (const float*)d_in[10];
    float* out = (float*)d_out;

    static cudaStream_t sA = nullptr, sB = nullptr;
    static cudaEvent_t evRoot = nullptr, evA = nullptr, evB = nullptr;
    if (sA == nullptr) {
        cudaStreamCreateWithFlags(&sA, cudaStreamNonBlocking);
        cudaStreamCreateWithFlags(&sB, cudaStreamNonBlocking);
        cudaEventCreateWithFlags(&evRoot, cudaEventDisableTiming);
        cudaEventCreateWithFlags(&evA, cudaEventDisableTiming);
        cudaEventCreateWithFlags(&evB, cudaEventDisableTiming);
        cudaFuncSetAttribute(gemm_kernel, cudaFuncAttributeMaxDynamicSharedMemorySize,
                             2 * GSTG);
    }

    int n4 = (TOK_ * H_) / 4;

    // ---- prologue on the capture (default) stream ----
    precompute_kernel<<<(NL_ * H_ * N_ + 255) / 256, 256>>>(log_dt, A_re_log, A_im, C_re, C_im);
    precompute_w_kernel<<<(int)(((size_t)NL_ * 2 * H_ * (H_ / 2)) / 256), 256>>>(W_out, b_out);
    copy_in_kernel<<<n4 / 256, 256>>>((const float4*)x);

    // ---- fork ----
    cudaEventRecord(evRoot, 0);
    cudaStreamWaitEvent(sA, evRoot, 0);
    cudaStreamWaitEvent(sB, evRoot, 0);

    cudaStream_t st[2] = {sA, sB};
    for (int layer = 0; layer < NL_; layer++) {
        for (int c = 0; c < 2; c++) {
            int b0 = c * BH_, tok0 = c * TOKH_, bh0 = b0 * H_;
            cudaStream_t s = st[c];
            ln_stats_kernel<<<TOKH_ / 8, 256, 0, s>>>(tok0);
            ln_apply_t_kernel<<<dim3(H_ / 32, L_ / 32, BH_), dim3(32, 8), 0, s>>>(
                ln_w, ln_b, layer, b0);
            scan_kernel<<<(BH_ * H_) / 8, 256, 0, s>>>(D_skip, layer, bh0);
            convert_kernel<<<dim3(H_ / 32, L_ / 32, BH_), dim3(32, 8), 0, s>>>(b0);
            gemm_kernel<<<dim3(2 * H_ / 128, TOKH_ / 128), 256, 2 * GSTG, s>>>(layer, tok0);
        }
    }

    // ---- join ----
    cudaEventRecord(evA, sA);
    cudaEventRecord(evB, sB);
    cudaStreamWaitEvent(0, evA, 0);
    cudaStreamWaitEvent(0, evB, 0);

    copy_out_kernel<<<n4 / 256, 256>>>((float4*)out);
}

// round 15
// speedup vs baseline: 1.1578x; 1.1578x over previous
#include <cuda_runtime.h>
#include <cuda_bf16.h>
#include <math.h>
#include <stdint.h>

#define B_ 8
#define L_ 1024
#define H_ 1024
#define N_ 32
#define NL_ 4
#define TOK_ (B_ * L_)        // 8192 tokens
#define BH_ (B_ / 2)          // batches per chain
#define TOKH_ (TOK_ / 2)      // tokens per chain

// ---------------- scratch (static device globals) -----------------------------------
__device__ float g_h[(size_t)TOK_ * H_];            // residual, token-major (B*L, H)
__device__ float g_z[(size_t)B_ * H_ * L_];         // post-LN, (B,H,L) for scan
__device__ float g_y[(size_t)B_ * H_ * L_];         // post scan+gelu, (B,H,L)
__device__ __nv_bfloat16 g_ahi[(size_t)TOK_ * H_];  // scan out, token-major bf16 hi
__device__ __nv_bfloat16 g_alo[(size_t)TOK_ * H_];  // bf16 lo
__device__ __nv_bfloat16 g_whi[(size_t)NL_ * 2 * H_ * H_];  // interleaved W, bf16 hi
__device__ __nv_bfloat16 g_wlo[(size_t)NL_ * 2 * H_ * H_];  // bf16 lo
__device__ float g_biasr[NL_ * 2 * H_];             // interleaved bias
__device__ float g_mu[TOK_];
__device__ float g_rs[TOK_];
__device__ float g_lam_re[NL_ * H_ * N_];
__device__ float g_lam_im[NL_ * H_ * N_];
__device__ float g_cp_re[NL_ * H_ * N_];
__device__ float g_cp_im[NL_ * H_ * N_];

// ---------------- PTX helpers (sm_80+ generic only; NO 'a'-features) -----------------
__device__ __forceinline__ uint32_t smem_u32(const void* p) {
    uint32_t a;
    asm("{ .reg .u64 t; cvta.to.shared.u64 t, %1; cvt.u32.u64 %0, t; }" : "=r"(a) : "l"(p));
    return a;
}
__device__ __forceinline__ void cp16(uint32_t s, const void* g) {
    asm volatile("cp.async.cg.shared.global [%0], [%1], 16;" :: "r"(s), "l"(g));
}
__device__ __forceinline__ void cp_commit() {
    asm volatile("cp.async.commit_group;" ::: "memory");
}
__device__ __forceinline__ void cp_wait1() {
    asm volatile("cp.async.wait_group 1;" ::: "memory");
}
#define SWZ(off) ((off) ^ (((off) >> 3) & 0x70))

__device__ __forceinline__ void ldmx4(uint32_t* r, uint32_t addr) {
    asm volatile("ldmatrix.sync.aligned.m8n8.x4.shared.b16 {%0,%1,%2,%3}, [%4];"
                 : "=r"(r[0]), "=r"(r[1]), "=r"(r[2]), "=r"(r[3]) : "r"(addr));
}
__device__ __forceinline__ void mma16816(float* c, const uint32_t* a, uint32_t b0, uint32_t b1) {
    asm volatile(
        "mma.sync.aligned.m16n8k16.row.col.f32.bf16.bf16.f32 "
        "{%0,%1,%2,%3}, {%4,%5,%6,%7}, {%8,%9}, {%0,%1,%2,%3};"
        : "+f"(c[0]), "+f"(c[1]), "+f"(c[2]), "+f"(c[3])
        : "r"(a[0]), "r"(a[1]), "r"(a[2]), "r"(a[3]), "r"(b0), "r"(b1));
}

// ---------------- precompute lambda / C' (fp64) --------------------------------------
__global__ void precompute_kernel(const float* __restrict__ log_dt,
                                  const float* __restrict__ A_re_log,
                                  const float* __restrict__ A_im,
                                  const float* __restrict__ C_re,
                                  const float* __restrict__ C_im) {
    int idx = blockIdx.x * blockDim.x + threadIdx.x;
    if (idx >= NL_ * H_ * N_) return;
    int lh = idx / N_;
    double dt  = exp((double)log_dt[lh]);
    double Are = -exp((double)A_re_log[idx]);
    double Aim = (double)A_im[idx];
    double dre = Are * dt, dim = Aim * dt;
    double er  = exp(dre);
    double lre = er * cos(dim), lim = er * sin(dim);
    g_lam_re[idx] = (float)lre;
    g_lam_im[idx] = (float)lim;
    double e1re = lre - 1.0, e1im = lim;
    double den  = Are * Are + Aim * Aim;
    double fre  = (e1re * Are + e1im * Aim) / den;
    double fim  = (e1im * Are - e1re * Aim) / den;
    double cr = (double)C_re[idx], ci = (double)C_im[idx];
    g_cp_re[idx] = (float)(cr * fre - ci * fim);
    g_cp_im[idx] = (float)(cr * fim + ci * fre);
}

// ---------------- W reorder+split: W'[l, 2o+s] = W[l, s?H+o:o], bf16 hi/lo -----------
__global__ void precompute_w_kernel(const float* __restrict__ W_out,
                                    const float* __restrict__ b_out) {
    size_t idx = (size_t)blockIdx.x * blockDim.x + threadIdx.x;
    if (idx >= (size_t)NL_ * 2 * H_ * H_) return;
    int k = (int)(idx & (H_ - 1));
    int n = (int)((idx >> 10) & (2 * H_ - 1));
    int layer = (int)(idx >> 21);
    int o = n >> 1, s = n & 1;
    int src_row = s ? (H_ + o) : o;
    float v = W_out[((size_t)layer * 2 * H_ + src_row) * H_ + k];
    __nv_bfloat16 hv = __float2bfloat16(v);
    float hf = __bfloat162float(hv);
    g_whi[idx] = hv;
    g_wlo[idx] = __float2bfloat16(v - hf);
    if (k == 0) g_biasr[layer * 2 * H_ + n] = b_out[layer * 2 * H_ + src_row];
}

// ---------------- copies --------------------------------------------------------------
__global__ void copy_in_kernel(const float4* __restrict__ src) {
    int i = blockIdx.x * blockDim.x + threadIdx.x;
    ((float4*)g_h)[i] = src[i];
}
__global__ void copy_out_kernel(float4* __restrict__ dst) {
    int i = blockIdx.x * blockDim.x + threadIdx.x;
    dst[i] = ((const float4*)g_h)[i];
}

// ---------------- LN stats: per-token mean / rstd (token-major g_h) ------------------
__global__ void ln_stats_kernel(int tok0) {
    int wid = threadIdx.x >> 5, lane = threadIdx.x & 31;
    int token = tok0 + blockIdx.x * 8 + wid;
    const float4* p = (const float4*)(g_h + (size_t)token * H_);
    float s = 0.f, ss = 0.f;
    #pragma unroll
    for (int j = 0; j < 8; j++) {
        float4 v = p[lane + j * 32];
        s  += v.x + v.y + v.z + v.w;
        ss += v.x * v.x + v.y * v.y + v.z * v.z + v.w * v.w;
    }
    #pragma unroll
    for (int o = 16; o > 0; o >>= 1) {
        s  += __shfl_xor_sync(0xffffffffu, s, o);
        ss += __shfl_xor_sync(0xffffffffu, ss, o);
    }
    if (lane == 0) {
        float mu = s * (1.0f / H_);
        float var = ss * (1.0f / H_) - mu * mu;
        g_mu[token] = mu;
        g_rs[token] = rsqrtf(var + 1e-5f);
    }
}

// ---------------- LN apply + transpose: g_h(token,H) -> g_z(B,H,L) -------------------
__global__ void ln_apply_t_kernel(const float* __restrict__ ln_w,
                                  const float* __restrict__ ln_b, int layer, int b0) {
    __shared__ float tile[32][33];
    int b = b0 + blockIdx.z;
    int h0 = blockIdx.x * 32, l0 = blockIdx.y * 32;
    int tx = threadIdx.x, ty = threadIdx.y;
    float w  = ln_w[layer * H_ + h0 + tx];
    float bb = ln_b[layer * H_ + h0 + tx];
    #pragma unroll
    for (int i = ty; i < 32; i += 8) {
        int token = b * L_ + l0 + i;
        float v = g_h[(size_t)token * H_ + h0 + tx];
        tile[i][tx] = (v - g_mu[token]) * g_rs[token] * w + bb;
    }
    __syncthreads();
    #pragma unroll
    for (int i = ty; i < 32; i += 8)
        g_z[(size_t)b * H_ * L_ + (size_t)(h0 + i) * L_ + l0 + tx] = tile[tx][i];
}

// ---------------- S4D scan + D_skip + gelu -------------------------------------------
// one warp per (b,h); lane n owns mode n. 2-step state batching:
//   s2 = lam^2 * s0 + lam*z0 + z1 ;  r1 = Re(C'lam * s0) + Re(C')*z0 ; r2 = Re(C'*s2)
// 11 FMA-pipe ops per 2 steps (vs 16 naive). Transpose-reduce pads to 36 floats
// (stride/4 = 9 odd -> conflict-free float4 reads, same summation order).
__global__ __launch_bounds__(256) void scan_kernel(const float* __restrict__ D_skip,
                                                   int layer, int bh0) {
    __shared__ float red[8][32 * 36];
    int warp = (blockIdx.x * blockDim.x + threadIdx.x) >> 5;
    int wip  = threadIdx.x >> 5;
    int lane = threadIdx.x & 31;
    int bh = bh0 + warp;
    int h  = bh & (H_ - 1);
    int pidx = (layer * H_ + h) * N_ + lane;
    float lr = g_lam_re[pidx], li = g_lam_im[pidx];
    float cr = g_cp_re[pidx],  ci = g_cp_im[pidx];
    // derived constants: lam^2 and d = C' * lam
    float l2r = lr * lr - li * li;
    float l2i = 2.0f * lr * li;
    float dr  = cr * lr - ci * li;
    float di  = cr * li + ci * lr;
    float D  = D_skip[layer * H_ + h];
    const float* zp = g_z + (size_t)bh * L_;
    float* yp = g_y + (size_t)bh * L_;
    float* rb = red[wip];
    float sre = 0.f, sim = 0.f;
    for (int l0 = 0; l0 < L_; l0 += 32) {
        const float4* zp4 = (const float4*)(zp + l0);
        float r[32];
        #pragma unroll
        for (int q = 0; q < 8; q++) {
            float4 zv = zp4[q];   // uniform address -> broadcast
            // steps 4q, 4q+1
            r[q * 4 + 0] = fmaf(dr, sre, fmaf(-di, sim, cr * zv.x));
            {
                float nre = fmaf(l2r, sre, fmaf(-l2i, sim, fmaf(lr, zv.x, zv.y)));
                float nim = fmaf(l2i, sre, fmaf(l2r, sim, li * zv.x));
                sre = nre; sim = nim;
            }
            r[q * 4 + 1] = fmaf(cr, sre, -ci * sim);
            // steps 4q+2, 4q+3
            r[q * 4 + 2] = fmaf(dr, sre, fmaf(-di, sim, cr * zv.z));
            {
                float nre = fmaf(l2r, sre, fmaf(-l2i, sim, fmaf(lr, zv.z, zv.w)));
                float nim = fmaf(l2i, sre, fmaf(l2r, sim, li * zv.z));
                sre = nre; sim = nim;
            }
            r[q * 4 + 3] = fmaf(cr, sre, -ci * sim);
        }
        // transpose-reduce: write r[j] to row j, column lane; read own row vectorized
        #pragma unroll
        for (int j = 0; j < 32; j++)
            rb[j * 36 + lane] = r[j];
        __syncwarp();
        const float4* row4 = (const float4*)(rb + lane * 36);
        float s0 = 0.f, s1 = 0.f, s2 = 0.f, s3 = 0.f;
        #pragma unroll
        for (int q = 0; q < 8; q++) {
            float4 v = row4[q];
            s0 += v.x; s1 += v.y; s2 += v.z; s3 += v.w;
        }
        float sum = (s0 + s1) + (s2 + s3);
        __syncwarp();
        float z  = zp[l0 + lane];
        float xv = 2.0f * sum + D * z;
        float u  = 0.7978845608028654f * (xv + 0.044715f * xv * xv * xv);
        float t  = tanhf(u);
        yp[l0 + lane] = 0.5f * xv * (1.0f + t);
    }
}

// ---------------- convert+transpose: g_y(B,H,L) -> a_hi/a_lo (token,H) bf16 ----------
__global__ void convert_kernel(int b0) {
    __shared__ float tile[32][33];
    int b = b0 + blockIdx.z;
    int h0 = blockIdx.x * 32, l0 = blockIdx.y * 32;
    int tx = threadIdx.x, ty = threadIdx.y;
    #pragma unroll
    for (int i = ty; i < 32; i += 8)
        tile[i][tx] = g_y[(size_t)b * H_ * L_ + (size_t)(h0 + i) * L_ + l0 + tx];
    __syncthreads();
    #pragma unroll
    for (int i = ty; i < 32; i += 8) {
        float v = tile[tx][i];
        __nv_bfloat16 hv = __float2bfloat16(v);
        float hf = __bfloat162float(hv);
        size_t idx = ((size_t)(b * L_ + l0 + i)) * H_ + h0 + tx;
        g_ahi[idx] = hv;
        g_alo[idx] = __float2bfloat16(v - hf);
    }
}

// ---------------- mma.sync bf16 GEMM + fused bias/GLU/residual (R10, unchanged) ------
// CTA tile 128(m) x 256(n); K=1024 in 16 chunks of 64. Per chunk: load Ahi/Alo/Whi/Wlo
// once, issue 3 products (Ahi*Whi + Alo*Whi + Ahi*Wlo) into one accumulator.
// 512 threads = 16 warps, warp tile 32(m) x 64(n), m16n8k16.
#define G_KC 64
#define G_NCHUNK 16
#define G_STAGE_BYTES 98304     // Ahi 16K | Alo 16K | Whi 32K | Wlo 32K
#define G_OFF_ALO 16384u
#define G_OFF_WHI 32768u
#define G_OFF_WLO 65536u

__device__ __forceinline__ void fetch_chunk(uint32_t base, int c, int m0, int n0,
                                            const __nv_bfloat16* whiL,
                                            const __nv_bfloat16* wloL, int tid) {
    int k0 = c * G_KC;
    uint32_t st = base + (uint32_t)(c & 1) * G_STAGE_BYTES;
    #pragma unroll
    for (int i = 0; i < 2; i++) {          // Ahi: 128 rows x 128B
        int seg = tid + i * 512, row = seg >> 3, sg = seg & 7;
        cp16(st + SWZ(row * 128 + sg * 16),
             g_ahi + (size_t)(m0 + row) * H_ + k0 + sg * 8);
    }
    #pragma unroll
    for (int i = 0; i < 2; i++) {          // Alo
        int seg = tid + i * 512, row = seg >> 3, sg = seg & 7;
        cp16(st + G_OFF_ALO + SWZ(row * 128 + sg * 16),
             g_alo + (size_t)(m0 + row) * H_ + k0 + sg * 8);
    }
    #pragma unroll
    for (int i = 0; i < 4; i++) {          // Whi: 256 rows x 128B
        int seg = tid + i * 512, row = seg >> 3, sg = seg & 7;
        cp16(st + G_OFF_WHI + SWZ(row * 128 + sg * 16),
             whiL + (size_t)(n0 + row) * H_ + k0 + sg * 8);
    }
    #pragma unroll
    for (int i = 0; i < 4; i++) {          // Wlo
        int seg = tid + i * 512, row = seg >> 3, sg = seg & 7;
        cp16(st + G_OFF_WLO + SWZ(row * 128 + sg * 16),
             wloL + (size_t)(n0 + row) * H_ + k0 + sg * 8);
    }
}

__global__ __launch_bounds__(512, 1) void gemm_kernel(int layer, int tok0) {
    extern __shared__ __align__(1024) char dsm[];
    uint32_t base = smem_u32(dsm);
    int tid = threadIdx.x, lane = tid & 31, wid = tid >> 5;
    int warp_m = wid & 3, warp_n = wid >> 2;      // 4 x 4 warps
    int n0 = blockIdx.x * 256;
    int m0 = tok0 + blockIdx.y * 128;

    const __nv_bfloat16* whiL = g_whi + (size_t)layer * 2 * H_ * H_;
    const __nv_bfloat16* wloL = g_wlo + (size_t)layer * 2 * H_ * H_;

    // per-lane ldmatrix row constants
    int grp = lane >> 3, idx8 = lane & 7;
    int r8 = (grp & 1) * 8 + idx8;
    uint32_t klane = (uint32_t)(grp >> 1) * 16;   // 0 or 16
    uint32_t aoff[2], axor[2], boff[4], bxor[4];
    #pragma unroll
    for (int mt = 0; mt < 2; mt++) {
        int row = warp_m * 32 + mt * 16 + r8;
        aoff[mt] = (uint32_t)row * 128;
        axor[mt] = (uint32_t)(row & 7) << 4;
    }
    #pragma unroll
    for (int nt2 = 0; nt2 < 4; nt2++) {
        int row = warp_n * 64 + nt2 * 16 + r8;
        boff[nt2] = G_OFF_WHI + (uint32_t)row * 128;
        bxor[nt2] = (uint32_t)(row & 7) << 4;
    }

    float acc[2][8][4];
    #pragma unroll
    for (int mt = 0; mt < 2; mt++)
        #pragma unroll
        for (int nt = 0; nt < 8; nt++)
            #pragma unroll
            for (int u = 0; u < 4; u++) acc[mt][nt][u] = 0.f;

    fetch_chunk(base, 0, m0, n0, whiL, wloL, tid);
    cp_commit();

    for (int c = 0; c < G_NCHUNK; c++) {
        if (c + 1 < G_NCHUNK) fetch_chunk(base, c + 1, m0, n0, whiL, wloL, tid);
        cp_commit();
        cp_wait1();                // chunk c resident
        __syncthreads();

        uint32_t stage = base + (uint32_t)(c & 1) * G_STAGE_BYTES;
        #pragma unroll
        for (int ks = 0; ks < 4; ks++) {
            uint32_t kb = (uint32_t)ks * 32 + klane;
            uint32_t ah[2][4], al[2][4];
            #pragma unroll
            for (int mt = 0; mt < 2; mt++) {
                ldmx4(ah[mt], stage + aoff[mt] + (kb ^ axor[mt]));
                ldmx4(al[mt], stage + aoff[mt] + G_OFF_ALO + (kb ^ axor[mt]));
            }
            uint32_t w[4][4];
            #pragma unroll
            for (int nt2 = 0; nt2 < 4; nt2++)
                ldmx4(w[nt2], stage + boff[nt2] + (kb ^ bxor[nt2]));      // Whi
            #pragma unroll
            for (int mt = 0; mt < 2; mt++)
                #pragma unroll
                for (int nt2 = 0; nt2 < 4; nt2++) {
                    mma16816(acc[mt][2 * nt2],     ah[mt], w[nt2][0], w[nt2][2]);
                    mma16816(acc[mt][2 * nt2 + 1], ah[mt], w[nt2][1], w[nt2][3]);
                    mma16816(acc[mt][2 * nt2],     al[mt], w[nt2][0], w[nt2][2]);
                    mma16816(acc[mt][2 * nt2 + 1], al[mt], w[nt2][1], w[nt2][3]);
                }
            #pragma unroll
            for (int nt2 = 0; nt2 < 4; nt2++)
                ldmx4(w[nt2], stage + boff[nt2] + 32768u + (kb ^ bxor[nt2])); // Wlo
            #pragma unroll
            for (int mt = 0; mt < 2; mt++)
                #pragma unroll
                for (int nt2 = 0; nt2 < 4; nt2++) {
                    mma16816(acc[mt][2 * nt2],     ah[mt], w[nt2][0], w[nt2][2]);
                    mma16816(acc[mt][2 * nt2 + 1], ah[mt], w[nt2][1], w[nt2][3]);
                }
        }
        __syncthreads();           // protect stage (c&1) before fetch (c+2) overwrites
    }

    // epilogue: bias + GLU (adjacent interleaved col pairs in-thread) + residual
    int g = lane >> 2, tig = lane & 3;
    const float* bp = g_biasr + layer * 2 * H_;
    #pragma unroll
    for (int mt = 0; mt < 2; mt++) {
        int mrow = m0 + warp_m * 32 + mt * 16 + g;
        float* hr0 = g_h + (size_t)mrow * H_;
        float* hr1 = hr0 + (size_t)8 * H_;
        #pragma unroll
        for (int nt = 0; nt < 8; nt++) {
            int ncol = n0 + warp_n * 64 + nt * 8 + 2 * tig;  // even
            float b1v = bp[ncol], b2v = bp[ncol + 1];
            int hcol = ncol >> 1;
            float o1 = acc[mt][nt][0] + b1v;
            float o2 = acc[mt][nt][1] + b2v;
            hr0[hcol] += o1 / (1.0f + expf(-o2));
            o1 = acc[mt][nt][2] + b1v;
            o2 = acc[mt][nt][3] + b2v;
            hr1[hcol] += o1 / (1.0f + expf(-o2));
        }
    }
}

// ---------------- launch -------------------------------------------------------------
// R10 stream topology (plain fork, two batch-half chains) — best measured.
extern "C" void kernel_launch(void* const* d_in, const int* in_sizes, int n_in,
                              void* d_out, int out_size) {
    const float* x        = (const float*)d_in[0];
    const float* ln_w     = (const float*)d_in[1];
    const float* ln_b     = (const float*)d_in[2];
    const float* log_dt   = (const float*)d_in[3];
    const float* A_re_log = (const float*)d_in[4];
    const float* A_im     = (const float*)d_in[5];
    const float* C_re     = (const float*)d_in[6];
    const float* C_im     = (const float*)d_in[7];
    const float* D_skip   = (const float*)d_in[8];
    const float* W_out    = (const float*)d_in[9];
    const float* b_out    = (const float*)d_in[10];
    float* out = (float*)d_out;

    // one-time resources (handles identical on every call -> deterministic graph)
    static cudaStream_t sA = nullptr, sB = nullptr;
    static cudaEvent_t evRoot = nullptr, evA = nullptr, evB = nullptr;
    if (sA == nullptr) {
        cudaStreamCreateWithFlags(&sA, cudaStreamNonBlocking);
        cudaStreamCreateWithFlags(&sB, cudaStreamNonBlocking);
        cudaEventCreateWithFlags(&evRoot, cudaEventDisableTiming);
        cudaEventCreateWithFlags(&evA, cudaEventDisableTiming);
        cudaEventCreateWithFlags(&evB, cudaEventDisableTiming);
        cudaFuncSetAttribute(gemm_kernel, cudaFuncAttributeMaxDynamicSharedMemorySize,
                             2 * G_STAGE_BYTES);
    }

    int n4 = (TOK_ * H_) / 4;

    // ---- prologue on the capture (default) stream ----
    precompute_kernel<<<(NL_ * H_ * N_ + 255) / 256, 256>>>(log_dt, A_re_log, A_im, C_re, C_im);
    precompute_w_kernel<<<(int)(((size_t)NL_ * 2 * H_ * H_) / 256), 256>>>(W_out, b_out);
    copy_in_kernel<<<n4 / 256, 256>>>((const float4*)x);

    // ---- fork ----
    cudaEventRecord(evRoot, 0);
    cudaStreamWaitEvent(sA, evRoot, 0);
    cudaStreamWaitEvent(sB, evRoot, 0);

    cudaStream_t st[2] = {sA, sB};
    for (int layer = 0; layer < NL_; layer++) {
        for (int c = 0; c < 2; c++) {
            int b0 = c * BH_, tok0 = c * TOKH_, bh0 = b0 * H_;
            cudaStream_t s = st[c];
            ln_stats_kernel<<<TOKH_ / 8, 256, 0, s>>>(tok0);
            ln_apply_t_kernel<<<dim3(H_ / 32, L_ / 32, BH_), dim3(32, 8), 0, s>>>(
                ln_w, ln_b, layer, b0);
            scan_kernel<<<(BH_ * H_) / 8, 256, 0, s>>>(D_skip, layer, bh0);
            convert_kernel<<<dim3(H_ / 32, L_ / 32, BH_), dim3(32, 8), 0, s>>>(b0);
            gemm_kernel<<<dim3(2 * H_ / 256, TOKH_ / 128), 512, 2 * G_STAGE_BYTES, s>>>(
                layer, tok0);
        }
    }

    // ---- join ----
    cudaEventRecord(evA, sA);
    cudaEventRecord(evB, sB);
    cudaStreamWaitEvent(0, evA, 0);
    cudaStreamWaitEvent(0, evB, 0);

    copy_out_kernel<<<n4 / 256, 256>>>((float4*)out);
}

// round 16
// speedup vs baseline: 1.4312x; 1.2361x over previous
#include <cuda_runtime.h>
#include <cuda_fp16.h>
#include <math.h>
#include <stdint.h>

#define B_ 8
#define L_ 1024
#define H_ 1024
#define N_ 32
#define NL_ 4
#define TOK_ (B_ * L_)        // 8192 tokens
#define BH_ (B_ / 2)          // batches per chain
#define TOKH_ (TOK_ / 2)      // tokens per chain

// ---------------- scratch (static device globals) -----------------------------------
__device__ float g_h[(size_t)TOK_ * H_];            // residual, token-major (B*L, H)
__device__ float g_z[(size_t)B_ * H_ * L_];         // post-LN, (B,H,L) for scan
__device__ float g_y[(size_t)B_ * H_ * L_];         // post scan+gelu, (B,H,L)
__device__ __half g_ahi[(size_t)TOK_ * H_];         // scan out, token-major fp16 hi
__device__ __half g_alo[(size_t)TOK_ * H_];         // fp16 lo (A - Ahi)
__device__ __half g_w16[(size_t)NL_ * 2 * H_ * H_]; // interleaved W, single fp16
__device__ float g_biasr[NL_ * 2 * H_];             // interleaved bias
__device__ float g_mu[TOK_];
__device__ float g_rs[TOK_];
__device__ float g_lam_re[NL_ * H_ * N_];
__device__ float g_lam_im[NL_ * H_ * N_];
__device__ float g_cp_re[NL_ * H_ * N_];
__device__ float g_cp_im[NL_ * H_ * N_];

// ---------------- PTX helpers (sm_80+ generic only; NO 'a'-features) -----------------
__device__ __forceinline__ uint32_t smem_u32(const void* p) {
    uint32_t a;
    asm("{ .reg .u64 t; cvta.to.shared.u64 t, %1; cvt.u32.u64 %0, t; }" : "=r"(a) : "l"(p));
    return a;
}
__device__ __forceinline__ void cp16(uint32_t s, const void* g) {
    asm volatile("cp.async.cg.shared.global [%0], [%1], 16;" :: "r"(s), "l"(g));
}
__device__ __forceinline__ void cp_commit() {
    asm volatile("cp.async.commit_group;" ::: "memory");
}
__device__ __forceinline__ void cp_wait1() {
    asm volatile("cp.async.wait_group 1;" ::: "memory");
}
#define SWZ(off) ((off) ^ (((off) >> 3) & 0x70))

__device__ __forceinline__ void ldmx4(uint32_t* r, uint32_t addr) {
    asm volatile("ldmatrix.sync.aligned.m8n8.x4.shared.b16 {%0,%1,%2,%3}, [%4];"
                 : "=r"(r[0]), "=r"(r[1]), "=r"(r[2]), "=r"(r[3]) : "r"(addr));
}
// fp16 mma with fp32 accumulate (sm_80+ generic)
__device__ __forceinline__ void mma16816(float* c, const uint32_t* a, uint32_t b0, uint32_t b1) {
    asm volatile(
        "mma.sync.aligned.m16n8k16.row.col.f32.f16.f16.f32 "
        "{%0,%1,%2,%3}, {%4,%5,%6,%7}, {%8,%9}, {%0,%1,%2,%3};"
        : "+f"(c[0]), "+f"(c[1]), "+f"(c[2]), "+f"(c[3])
        : "r"(a[0]), "r"(a[1]), "r"(a[2]), "r"(a[3]), "r"(b0), "r"(b1));
}

// ---------------- precompute lambda / C' (fp64) --------------------------------------
__global__ void precompute_kernel(const float* __restrict__ log_dt,
                                  const float* __restrict__ A_re_log,
                                  const float* __restrict__ A_im,
                                  const float* __restrict__ C_re,
                                  const float* __restrict__ C_im) {
    int idx = blockIdx.x * blockDim.x + threadIdx.x;
    if (idx >= NL_ * H_ * N_) return;
    int lh = idx / N_;
    double dt  = exp((double)log_dt[lh]);
    double Are = -exp((double)A_re_log[idx]);
    double Aim = (double)A_im[idx];
    double dre = Are * dt, dim = Aim * dt;
    double er  = exp(dre);
    double lre = er * cos(dim), lim = er * sin(dim);
    g_lam_re[idx] = (float)lre;
    g_lam_im[idx] = (float)lim;
    double e1re = lre - 1.0, e1im = lim;
    double den  = Are * Are + Aim * Aim;
    double fre  = (e1re * Are + e1im * Aim) / den;
    double fim  = (e1im * Are - e1re * Aim) / den;
    double cr = (double)C_re[idx], ci = (double)C_im[idx];
    g_cp_re[idx] = (float)(cr * fre - ci * fim);
    g_cp_im[idx] = (float)(cr * fim + ci * fre);
}

// ---------------- W reorder: W'[l, 2o+s] = W[l, s?H+o:o], single fp16 ----------------
__global__ void precompute_w_kernel(const float* __restrict__ W_out,
                                    const float* __restrict__ b_out) {
    size_t idx = (size_t)blockIdx.x * blockDim.x + threadIdx.x;
    if (idx >= (size_t)NL_ * 2 * H_ * H_) return;
    int k = (int)(idx & (H_ - 1));
    int n = (int)((idx >> 10) & (2 * H_ - 1));
    int layer = (int)(idx >> 21);
    int o = n >> 1, s = n & 1;
    int src_row = s ? (H_ + o) : o;
    float v = W_out[((size_t)layer * 2 * H_ + src_row) * H_ + k];
    g_w16[idx] = __float2half(v);
    if (k == 0) g_biasr[layer * 2 * H_ + n] = b_out[layer * 2 * H_ + src_row];
}

// ---------------- copies --------------------------------------------------------------
__global__ void copy_in_kernel(const float4* __restrict__ src) {
    int i = blockIdx.x * blockDim.x + threadIdx.x;
    ((float4*)g_h)[i] = src[i];
}
__global__ void copy_out_kernel(float4* __restrict__ dst) {
    int i = blockIdx.x * blockDim.x + threadIdx.x;
    dst[i] = ((const float4*)g_h)[i];
}

// ---------------- LN stats: per-token mean / rstd (token-major g_h) ------------------
__global__ void ln_stats_kernel(int tok0) {
    int wid = threadIdx.x >> 5, lane = threadIdx.x & 31;
    int token = tok0 + blockIdx.x * 8 + wid;
    const float4* p = (const float4*)(g_h + (size_t)token * H_);
    float s = 0.f, ss = 0.f;
    #pragma unroll
    for (int j = 0; j < 8; j++) {
        float4 v = p[lane + j * 32];
        s  += v.x + v.y + v.z + v.w;
        ss += v.x * v.x + v.y * v.y + v.z * v.z + v.w * v.w;
    }
    #pragma unroll
    for (int o = 16; o > 0; o >>= 1) {
        s  += __shfl_xor_sync(0xffffffffu, s, o);
        ss += __shfl_xor_sync(0xffffffffu, ss, o);
    }
    if (lane == 0) {
        float mu = s * (1.0f / H_);
        float var = ss * (1.0f / H_) - mu * mu;
        g_mu[token] = mu;
        g_rs[token] = rsqrtf(var + 1e-5f);
    }
}

// ---------------- LN apply + transpose: g_h(token,H) -> g_z(B,H,L) -------------------
__global__ void ln_apply_t_kernel(const float* __restrict__ ln_w,
                                  const float* __restrict__ ln_b, int layer, int b0) {
    __shared__ float tile[32][33];
    int b = b0 + blockIdx.z;
    int h0 = blockIdx.x * 32, l0 = blockIdx.y * 32;
    int tx = threadIdx.x, ty = threadIdx.y;
    float w  = ln_w[layer * H_ + h0 + tx];
    float bb = ln_b[layer * H_ + h0 + tx];
    #pragma unroll
    for (int i = ty; i < 32; i += 8) {
        int token = b * L_ + l0 + i;
        float v = g_h[(size_t)token * H_ + h0 + tx];
        tile[i][tx] = (v - g_mu[token]) * g_rs[token] * w + bb;
    }
    __syncthreads();
    #pragma unroll
    for (int i = ty; i < 32; i += 8)
        g_z[(size_t)b * H_ * L_ + (size_t)(h0 + i) * L_ + l0 + tx] = tile[tx][i];
}

// ---------------- S4D scan + D_skip + gelu (R15 version — verified fast) -------------
__global__ __launch_bounds__(256) void scan_kernel(const float* __restrict__ D_skip,
                                                   int layer, int bh0) {
    __shared__ float red[8][32 * 36];
    int warp = (blockIdx.x * blockDim.x + threadIdx.x) >> 5;
    int wip  = threadIdx.x >> 5;
    int lane = threadIdx.x & 31;
    int bh = bh0 + warp;
    int h  = bh & (H_ - 1);
    int pidx = (layer * H_ + h) * N_ + lane;
    float lr = g_lam_re[pidx], li = g_lam_im[pidx];
    float cr = g_cp_re[pidx],  ci = g_cp_im[pidx];
    float l2r = lr * lr - li * li;
    float l2i = 2.0f * lr * li;
    float dr  = cr * lr - ci * li;
    float di  = cr * li + ci * lr;
    float D  = D_skip[layer * H_ + h];
    const float* zp = g_z + (size_t)bh * L_;
    float* yp = g_y + (size_t)bh * L_;
    float* rb = red[wip];
    float sre = 0.f, sim = 0.f;
    for (int l0 = 0; l0 < L_; l0 += 32) {
        const float4* zp4 = (const float4*)(zp + l0);
        float r[32];
        #pragma unroll
        for (int q = 0; q < 8; q++) {
            float4 zv = zp4[q];   // uniform address -> broadcast
            r[q * 4 + 0] = fmaf(dr, sre, fmaf(-di, sim, cr * zv.x));
            {
                float nre = fmaf(l2r, sre, fmaf(-l2i, sim, fmaf(lr, zv.x, zv.y)));
                float nim = fmaf(l2i, sre, fmaf(l2r, sim, li * zv.x));
                sre = nre; sim = nim;
            }
            r[q * 4 + 1] = fmaf(cr, sre, -ci * sim);
            r[q * 4 + 2] = fmaf(dr, sre, fmaf(-di, sim, cr * zv.z));
            {
                float nre = fmaf(l2r, sre, fmaf(-l2i, sim, fmaf(lr, zv.z, zv.w)));
                float nim = fmaf(l2i, sre, fmaf(l2r, sim, li * zv.z));
                sre = nre; sim = nim;
            }
            r[q * 4 + 3] = fmaf(cr, sre, -ci * sim);
        }
        #pragma unroll
        for (int j = 0; j < 32; j++)
            rb[j * 36 + lane] = r[j];
        __syncwarp();
        const float4* row4 = (const float4*)(rb + lane * 36);
        float s0 = 0.f, s1 = 0.f, s2 = 0.f, s3 = 0.f;
        #pragma unroll
        for (int q = 0; q < 8; q++) {
            float4 v = row4[q];
            s0 += v.x; s1 += v.y; s2 += v.z; s3 += v.w;
        }
        float sum = (s0 + s1) + (s2 + s3);
        __syncwarp();
        float z  = zp[l0 + lane];
        float xv = 2.0f * sum + D * z;
        float u  = 0.7978845608028654f * (xv + 0.044715f * xv * xv * xv);
        float t  = tanhf(u);
        yp[l0 + lane] = 0.5f * xv * (1.0f + t);
    }
}

// ---------------- convert+transpose: g_y(B,H,L) -> a_hi/a_lo (token,H) fp16 ----------
__global__ void convert_kernel(int b0) {
    __shared__ float tile[32][33];
    int b = b0 + blockIdx.z;
    int h0 = blockIdx.x * 32, l0 = blockIdx.y * 32;
    int tx = threadIdx.x, ty = threadIdx.y;
    #pragma unroll
    for (int i = ty; i < 32; i += 8)
        tile[i][tx] = g_y[(size_t)b * H_ * L_ + (size_t)(h0 + i) * L_ + l0 + tx];
    __syncthreads();
    #pragma unroll
    for (int i = ty; i < 32; i += 8) {
        float v = tile[tx][i];
        __half hv = __float2half(v);
        float hf = __half2float(hv);
        size_t idx = ((size_t)(b * L_ + l0 + i)) * H_ + h0 + tx;
        g_ahi[idx] = hv;
        g_alo[idx] = __float2half(v - hf);
    }
}

// ---------------- mma.sync fp16 GEMM (2-product) + fused bias/GLU/residual -----------
// CTA tile 128(m) x 256(n); K=1024 in 16 chunks of 64. Per chunk: load Ahi/Alo/W
// once, 2 products ((Ahi + Alo) * W) into one accumulator. 128 HMMA/chunk (was 192).
// 512 threads = 16 warps, warp tile 32(m) x 64(n), m16n8k16 f16.
#define G_KC 64
#define G_NCHUNK 16
#define G_STAGE_BYTES 65536     // Ahi 16K | Alo 16K | W 32K
#define G_OFF_ALO 16384u
#define G_OFF_W   32768u

__device__ __forceinline__ void fetch_chunk(uint32_t base, int c, int m0, int n0,
                                            const __half* wL, int tid) {
    int k0 = c * G_KC;
    uint32_t st = base + (uint32_t)(c & 1) * G_STAGE_BYTES;
    #pragma unroll
    for (int i = 0; i < 2; i++) {          // Ahi: 128 rows x 128B
        int seg = tid + i * 512, row = seg >> 3, sg = seg & 7;
        cp16(st + SWZ(row * 128 + sg * 16),
             g_ahi + (size_t)(m0 + row) * H_ + k0 + sg * 8);
    }
    #pragma unroll
    for (int i = 0; i < 2; i++) {          // Alo
        int seg = tid + i * 512, row = seg >> 3, sg = seg & 7;
        cp16(st + G_OFF_ALO + SWZ(row * 128 + sg * 16),
             g_alo + (size_t)(m0 + row) * H_ + k0 + sg * 8);
    }
    #pragma unroll
    for (int i = 0; i < 4; i++) {          // W: 256 rows x 128B
        int seg = tid + i * 512, row = seg >> 3, sg = seg & 7;
        cp16(st + G_OFF_W + SWZ(row * 128 + sg * 16),
             wL + (size_t)(n0 + row) * H_ + k0 + sg * 8);
    }
}

__global__ __launch_bounds__(512, 1) void gemm_kernel(int layer, int tok0) {
    extern __shared__ __align__(1024) char dsm[];
    uint32_t base = smem_u32(dsm);
    int tid = threadIdx.x, lane = tid & 31, wid = tid >> 5;
    int warp_m = wid & 3, warp_n = wid >> 2;      // 4 x 4 warps
    int n0 = blockIdx.x * 256;
    int m0 = tok0 + blockIdx.y * 128;

    const __half* wL = g_w16 + (size_t)layer * 2 * H_ * H_;

    // per-lane ldmatrix row constants
    int grp = lane >> 3, idx8 = lane & 7;
    int r8 = (grp & 1) * 8 + idx8;
    uint32_t klane = (uint32_t)(grp >> 1) * 16;   // 0 or 16
    uint32_t aoff[2], axor[2], boff[4], bxor[4];
    #pragma unroll
    for (int mt = 0; mt < 2; mt++) {
        int row = warp_m * 32 + mt * 16 + r8;
        aoff[mt] = (uint32_t)row * 128;
        axor[mt] = (uint32_t)(row & 7) << 4;
    }
    #pragma unroll
    for (int nt2 = 0; nt2 < 4; nt2++) {
        int row = warp_n * 64 + nt2 * 16 + r8;
        boff[nt2] = G_OFF_W + (uint32_t)row * 128;
        bxor[nt2] = (uint32_t)(row & 7) << 4;
    }

    float acc[2][8][4];
    #pragma unroll
    for (int mt = 0; mt < 2; mt++)
        #pragma unroll
        for (int nt = 0; nt < 8; nt++)
            #pragma unroll
            for (int u = 0; u < 4; u++) acc[mt][nt][u] = 0.f;

    fetch_chunk(base, 0, m0, n0, wL, tid);
    cp_commit();

    for (int c = 0; c < G_NCHUNK; c++) {
        if (c + 1 < G_NCHUNK) fetch_chunk(base, c + 1, m0, n0, wL, tid);
        cp_commit();
        cp_wait1();                // chunk c resident
        __syncthreads();

        uint32_t stage = base + (uint32_t)(c & 1) * G_STAGE_BYTES;
        #pragma unroll
        for (int ks = 0; ks < 4; ks++) {
            uint32_t kb = (uint32_t)ks * 32 + klane;
            uint32_t ah[2][4], al[2][4];
            #pragma unroll
            for (int mt = 0; mt < 2; mt++) {
                ldmx4(ah[mt], stage + aoff[mt] + (kb ^ axor[mt]));
                ldmx4(al[mt], stage + aoff[mt] + G_OFF_ALO + (kb ^ axor[mt]));
            }
            uint32_t w[4][4];
            #pragma unroll
            for (int nt2 = 0; nt2 < 4; nt2++)
                ldmx4(w[nt2], stage + boff[nt2] + (kb ^ bxor[nt2]));
            #pragma unroll
            for (int mt = 0; mt < 2; mt++)
                #pragma unroll
                for (int nt2 = 0; nt2 < 4; nt2++) {
                    mma16816(acc[mt][2 * nt2],     ah[mt], w[nt2][0], w[nt2][2]);
                    mma16816(acc[mt][2 * nt2 + 1], ah[mt], w[nt2][1], w[nt2][3]);
                    mma16816(acc[mt][2 * nt2],     al[mt], w[nt2][0], w[nt2][2]);
                    mma16816(acc[mt][2 * nt2 + 1], al[mt], w[nt2][1], w[nt2][3]);
                }
        }
        __syncthreads();           // protect stage (c&1) before fetch (c+2) overwrites
    }

    // epilogue: bias + GLU (adjacent interleaved col pairs in-thread) + residual
    int g = lane >> 2, tig = lane & 3;
    const float* bp = g_biasr + layer * 2 * H_;
    #pragma unroll
    for (int mt = 0; mt < 2; mt++) {
        int mrow = m0 + warp_m * 32 + mt * 16 + g;
        float* hr0 = g_h + (size_t)mrow * H_;
        float* hr1 = hr0 + (size_t)8 * H_;
        #pragma unroll
        for (int nt = 0; nt < 8; nt++) {
            int ncol = n0 + warp_n * 64 + nt * 8 + 2 * tig;  // even
            float b1v = bp[ncol], b2v = bp[ncol + 1];
            int hcol = ncol >> 1;
            float o1 = acc[mt][nt][0] + b1v;
            float o2 = acc[mt][nt][1] + b2v;
            hr0[hcol] += o1 / (1.0f + expf(-o2));
            o1 = acc[mt][nt][2] + b1v;
            o2 = acc[mt][nt][3] + b2v;
            hr1[hcol] += o1 / (1.0f + expf(-o2));
        }
    }
}

// ---------------- launch -------------------------------------------------------------
// R10 stream topology (plain fork, two batch-half chains) — best measured.
extern "C" void kernel_launch(void* const* d_in, const int* in_sizes, int n_in,
                              void* d_out, int out_size) {
    const float* x        = (const float*)d_in[0];
    const float* ln_w     = (const float*)d_in[1];
    const float* ln_b     = (const float*)d_in[2];
    const float* log_dt   = (const float*)d_in[3];
    const float* A_re_log = (const float*)d_in[4];
    const float* A_im     = (const float*)d_in[5];
    const float* C_re     = (const float*)d_in[6];
    const float* C_im     = (const float*)d_in[7];
    const float* D_skip   = (const float*)d_in[8];
    const float* W_out    = (const float*)d_in[9];
    const float* b_out    = (const float*)d_in[10];
    float* out = (float*)d_out;

    static cudaStream_t sA = nullptr, sB = nullptr;
    static cudaEvent_t evRoot = nullptr, evA = nullptr, evB = nullptr;
    if (sA == nullptr) {
        cudaStreamCreateWithFlags(&sA, cudaStreamNonBlocking);
        cudaStreamCreateWithFlags(&sB, cudaStreamNonBlocking);
        cudaEventCreateWithFlags(&evRoot, cudaEventDisableTiming);
        cudaEventCreateWithFlags(&evA, cudaEventDisableTiming);
        cudaEventCreateWithFlags(&evB, cudaEventDisableTiming);
        cudaFuncSetAttribute(gemm_kernel, cudaFuncAttributeMaxDynamicSharedMemorySize,
                             2 * G_STAGE_BYTES);
    }

    int n4 = (TOK_ * H_) / 4;

    // ---- prologue on the capture (default) stream ----
    precompute_kernel<<<(NL_ * H_ * N_ + 255) / 256, 256>>>(log_dt, A_re_log, A_im, C_re, C_im);
    precompute_w_kernel<<<(int)(((size_t)NL_ * 2 * H_ * H_) / 256), 256>>>(W_out, b_out);
    copy_in_kernel<<<n4 / 256, 256>>>((const float4*)x);

    // ---- fork ----
    cudaEventRecord(evRoot, 0);
    cudaStreamWaitEvent(sA, evRoot, 0);
    cudaStreamWaitEvent(sB, evRoot, 0);

    cudaStream_t st[2] = {sA, sB};
    for (int layer = 0; layer < NL_; layer++) {
        for (int c = 0; c < 2; c++) {
            int b0 = c * BH_, tok0 = c * TOKH_, bh0 = b0 * H_;
            cudaStream_t s = st[c];
            ln_stats_kernel<<<TOKH_ / 8, 256, 0, s>>>(tok0);
            ln_apply_t_kernel<<<dim3(H_ / 32, L_ / 32, BH_), dim3(32, 8), 0, s>>>(
                ln_w, ln_b, layer, b0);
            scan_kernel<<<(BH_ * H_) / 8, 256, 0, s>>>(D_skip, layer, bh0);
            convert_kernel<<<dim3(H_ / 32, L_ / 32, BH_), dim3(32, 8), 0, s>>>(b0);
            gemm_kernel<<<dim3(2 * H_ / 256, TOKH_ / 128), 512, 2 * G_STAGE_BYTES, s>>>(
                layer, tok0);
        }
    }

    // ---- join ----
    cudaEventRecord(evA, sA);
    cudaEventRecord(evB, sB);
    cudaStreamWaitEvent(0, evA, 0);
    cudaStreamWaitEvent(0, evB, 0);

    copy_out_kernel<<<n4 / 256, 256>>>((float4*)out);
}

// round 17
// speedup vs baseline: 1.8223x; 1.2733x over previous
#include <cuda_runtime.h>
#include <cuda_fp16.h>
#include <math.h>
#include <stdint.h>

#define B_ 8
#define L_ 1024
#define H_ 1024
#define N_ 32
#define NL_ 4
#define TOK_ (B_ * L_)        // 8192 tokens
#define BH_ (B_ / 2)          // batches per chain
#define TOKH_ (TOK_ / 2)      // tokens per chain

// ---------------- scratch (static device globals) -----------------------------------
__device__ float g_h[(size_t)TOK_ * H_];            // residual, token-major (B*L, H)
__device__ float g_z[(size_t)B_ * H_ * L_];         // post-LN, (B,H,L) for scan
__device__ float g_y[(size_t)B_ * H_ * L_];         // post scan+gelu, (B,H,L)
__device__ __half g_a16[(size_t)TOK_ * H_];         // scan out, token-major fp16
__device__ __half g_w16[(size_t)NL_ * 2 * H_ * H_]; // interleaved W, fp16
__device__ float g_biasr[NL_ * 2 * H_];             // interleaved bias
__device__ float g_mu[TOK_];
__device__ float g_rs[TOK_];
__device__ float g_lam_re[NL_ * H_ * N_];
__device__ float g_lam_im[NL_ * H_ * N_];
__device__ float g_cp_re[NL_ * H_ * N_];
__device__ float g_cp_im[NL_ * H_ * N_];

// ---------------- PTX helpers (sm_80+ generic only; NO 'a'-features) -----------------
__device__ __forceinline__ uint32_t smem_u32(const void* p) {
    uint32_t a;
    asm("{ .reg .u64 t; cvta.to.shared.u64 t, %1; cvt.u32.u64 %0, t; }" : "=r"(a) : "l"(p));
    return a;
}
__device__ __forceinline__ void cp16(uint32_t s, const void* g) {
    asm volatile("cp.async.cg.shared.global [%0], [%1], 16;" :: "r"(s), "l"(g));
}
__device__ __forceinline__ void cp_commit() {
    asm volatile("cp.async.commit_group;" ::: "memory");
}
__device__ __forceinline__ void cp_wait1() {
    asm volatile("cp.async.wait_group 1;" ::: "memory");
}
#define SWZ(off) ((off) ^ (((off) >> 3) & 0x70))

__device__ __forceinline__ void ldmx4(uint32_t* r, uint32_t addr) {
    asm volatile("ldmatrix.sync.aligned.m8n8.x4.shared.b16 {%0,%1,%2,%3}, [%4];"
                 : "=r"(r[0]), "=r"(r[1]), "=r"(r[2]), "=r"(r[3]) : "r"(addr));
}
// fp16 mma with fp32 accumulate (sm_80+ generic)
__device__ __forceinline__ void mma16816(float* c, const uint32_t* a, uint32_t b0, uint32_t b1) {
    asm volatile(
        "mma.sync.aligned.m16n8k16.row.col.f32.f16.f16.f32 "
        "{%0,%1,%2,%3}, {%4,%5,%6,%7}, {%8,%9}, {%0,%1,%2,%3};"
        : "+f"(c[0]), "+f"(c[1]), "+f"(c[2]), "+f"(c[3])
        : "r"(a[0]), "r"(a[1]), "r"(a[2]), "r"(a[3]), "r"(b0), "r"(b1));
}

// ---------------- precompute lambda / C' (fp64) --------------------------------------
__global__ void precompute_kernel(const float* __restrict__ log_dt,
                                  const float* __restrict__ A_re_log,
                                  const float* __restrict__ A_im,
                                  const float* __restrict__ C_re,
                                  const float* __restrict__ C_im) {
    int idx = blockIdx.x * blockDim.x + threadIdx.x;
    if (idx >= NL_ * H_ * N_) return;
    int lh = idx / N_;
    double dt  = exp((double)log_dt[lh]);
    double Are = -exp((double)A_re_log[idx]);
    double Aim = (double)A_im[idx];
    double dre = Are * dt, dim = Aim * dt;
    double er  = exp(dre);
    double lre = er * cos(dim), lim = er * sin(dim);
    g_lam_re[idx] = (float)lre;
    g_lam_im[idx] = (float)lim;
    double e1re = lre - 1.0, e1im = lim;
    double den  = Are * Are + Aim * Aim;
    double fre  = (e1re * Are + e1im * Aim) / den;
    double fim  = (e1im * Are - e1re * Aim) / den;
    double cr = (double)C_re[idx], ci = (double)C_im[idx];
    g_cp_re[idx] = (float)(cr * fre - ci * fim);
    g_cp_im[idx] = (float)(cr * fim + ci * fre);
}

// ---------------- W reorder: W'[l, 2o+s] = W[l, s?H+o:o], single fp16 ----------------
__global__ void precompute_w_kernel(const float* __restrict__ W_out,
                                    const float* __restrict__ b_out) {
    size_t idx = (size_t)blockIdx.x * blockDim.x + threadIdx.x;
    if (idx >= (size_t)NL_ * 2 * H_ * H_) return;
    int k = (int)(idx & (H_ - 1));
    int n = (int)((idx >> 10) & (2 * H_ - 1));
    int layer = (int)(idx >> 21);
    int o = n >> 1, s = n & 1;
    int src_row = s ? (H_ + o) : o;
    float v = W_out[((size_t)layer * 2 * H_ + src_row) * H_ + k];
    g_w16[idx] = __float2half(v);
    if (k == 0) g_biasr[layer * 2 * H_ + n] = b_out[layer * 2 * H_ + src_row];
}

// ---------------- copies --------------------------------------------------------------
__global__ void copy_in_kernel(const float4* __restrict__ src) {
    int i = blockIdx.x * blockDim.x + threadIdx.x;
    ((float4*)g_h)[i] = src[i];
}
__global__ void copy_out_kernel(float4* __restrict__ dst) {
    int i = blockIdx.x * blockDim.x + threadIdx.x;
    dst[i] = ((const float4*)g_h)[i];
}

// ---------------- LN stats: per-token mean / rstd (token-major g_h) ------------------
__global__ void ln_stats_kernel(int tok0) {
    int wid = threadIdx.x >> 5, lane = threadIdx.x & 31;
    int token = tok0 + blockIdx.x * 8 + wid;
    const float4* p = (const float4*)(g_h + (size_t)token * H_);
    float s = 0.f, ss = 0.f;
    #pragma unroll
    for (int j = 0; j < 8; j++) {
        float4 v = p[lane + j * 32];
        s  += v.x + v.y + v.z + v.w;
        ss += v.x * v.x + v.y * v.y + v.z * v.z + v.w * v.w;
    }
    #pragma unroll
    for (int o = 16; o > 0; o >>= 1) {
        s  += __shfl_xor_sync(0xffffffffu, s, o);
        ss += __shfl_xor_sync(0xffffffffu, ss, o);
    }
    if (lane == 0) {
        float mu = s * (1.0f / H_);
        float var = ss * (1.0f / H_) - mu * mu;
        g_mu[token] = mu;
        g_rs[token] = rsqrtf(var + 1e-5f);
    }
}

// ---------------- LN apply + transpose: g_h(token,H) -> g_z(B,H,L) -------------------
__global__ void ln_apply_t_kernel(const float* __restrict__ ln_w,
                                  const float* __restrict__ ln_b, int layer, int b0) {
    __shared__ float tile[32][33];
    int b = b0 + blockIdx.z;
    int h0 = blockIdx.x * 32, l0 = blockIdx.y * 32;
    int tx = threadIdx.x, ty = threadIdx.y;
    float w  = ln_w[layer * H_ + h0 + tx];
    float bb = ln_b[layer * H_ + h0 + tx];
    #pragma unroll
    for (int i = ty; i < 32; i += 8) {
        int token = b * L_ + l0 + i;
        float v = g_h[(size_t)token * H_ + h0 + tx];
        tile[i][tx] = (v - g_mu[token]) * g_rs[token] * w + bb;
    }
    __syncthreads();
    #pragma unroll
    for (int i = ty; i < 32; i += 8)
        g_z[(size_t)b * H_ * L_ + (size_t)(h0 + i) * L_ + l0 + tx] = tile[tx][i];
}

// ---------------- S4D scan + D_skip + gelu (R15 version — verified fast) -------------
__global__ __launch_bounds__(256) void scan_kernel(const float* __restrict__ D_skip,
                                                   int layer, int bh0) {
    __shared__ float red[8][32 * 36];
    int warp = (blockIdx.x * blockDim.x + threadIdx.x) >> 5;
    int wip  = threadIdx.x >> 5;
    int lane = threadIdx.x & 31;
    int bh = bh0 + warp;
    int h  = bh & (H_ - 1);
    int pidx = (layer * H_ + h) * N_ + lane;
    float lr = g_lam_re[pidx], li = g_lam_im[pidx];
    float cr = g_cp_re[pidx],  ci = g_cp_im[pidx];
    float l2r = lr * lr - li * li;
    float l2i = 2.0f * lr * li;
    float dr  = cr * lr - ci * li;
    float di  = cr * li + ci * lr;
    float D  = D_skip[layer * H_ + h];
    const float* zp = g_z + (size_t)bh * L_;
    float* yp = g_y + (size_t)bh * L_;
    float* rb = red[wip];
    float sre = 0.f, sim = 0.f;
    for (int l0 = 0; l0 < L_; l0 += 32) {
        const float4* zp4 = (const float4*)(zp + l0);
        float r[32];
        #pragma unroll
        for (int q = 0; q < 8; q++) {
            float4 zv = zp4[q];   // uniform address -> broadcast
            r[q * 4 + 0] = fmaf(dr, sre, fmaf(-di, sim, cr * zv.x));
            {
                float nre = fmaf(l2r, sre, fmaf(-l2i, sim, fmaf(lr, zv.x, zv.y)));
                float nim = fmaf(l2i, sre, fmaf(l2r, sim, li * zv.x));
                sre = nre; sim = nim;
            }
            r[q * 4 + 1] = fmaf(cr, sre, -ci * sim);
            r[q * 4 + 2] = fmaf(dr, sre, fmaf(-di, sim, cr * zv.z));
            {
                float nre = fmaf(l2r, sre, fmaf(-l2i, sim, fmaf(lr, zv.z, zv.w)));
                float nim = fmaf(l2i, sre, fmaf(l2r, sim, li * zv.z));
                sre = nre; sim = nim;
            }
            r[q * 4 + 3] = fmaf(cr, sre, -ci * sim);
        }
        #pragma unroll
        for (int j = 0; j < 32; j++)
            rb[j * 36 + lane] = r[j];
        __syncwarp();
        const float4* row4 = (const float4*)(rb + lane * 36);
        float s0 = 0.f, s1 = 0.f, s2 = 0.f, s3 = 0.f;
        #pragma unroll
        for (int q = 0; q < 8; q++) {
            float4 v = row4[q];
            s0 += v.x; s1 += v.y; s2 += v.z; s3 += v.w;
        }
        float sum = (s0 + s1) + (s2 + s3);
        __syncwarp();
        float z  = zp[l0 + lane];
        float xv = 2.0f * sum + D * z;
        float u  = 0.7978845608028654f * (xv + 0.044715f * xv * xv * xv);
        float t  = tanhf(u);
        yp[l0 + lane] = 0.5f * xv * (1.0f + t);
    }
}

// ---------------- convert+transpose: g_y(B,H,L) -> a16 (token,H) fp16 ----------------
__global__ void convert_kernel(int b0) {
    __shared__ float tile[32][33];
    int b = b0 + blockIdx.z;
    int h0 = blockIdx.x * 32, l0 = blockIdx.y * 32;
    int tx = threadIdx.x, ty = threadIdx.y;
    #pragma unroll
    for (int i = ty; i < 32; i += 8)
        tile[i][tx] = g_y[(size_t)b * H_ * L_ + (size_t)(h0 + i) * L_ + l0 + tx];
    __syncthreads();
    #pragma unroll
    for (int i = ty; i < 32; i += 8) {
        float v = tile[tx][i];
        size_t idx = ((size_t)(b * L_ + l0 + i)) * H_ + h0 + tx;
        g_a16[idx] = __float2half(v);
    }
}

// ---------------- mma.sync fp16 GEMM (single product) + fused bias/GLU/residual ------
// CTA tile 128(m) x 256(n); K=1024 in 16 chunks of 64. One product A*W per chunk:
// 64 HMMA/chunk. 512 threads = 16 warps, warp tile 32(m) x 64(n), m16n8k16 f16.
#define G_KC 64
#define G_NCHUNK 16
#define G_STAGE_BYTES 49152     // A 16K | W 32K
#define G_OFF_W 16384u

__device__ __forceinline__ void fetch_chunk(uint32_t base, int c, int m0, int n0,
                                            const __half* wL, int tid) {
    int k0 = c * G_KC;
    uint32_t st = base + (uint32_t)(c & 1) * G_STAGE_BYTES;
    #pragma unroll
    for (int i = 0; i < 2; i++) {          // A: 128 rows x 128B
        int seg = tid + i * 512, row = seg >> 3, sg = seg & 7;
        cp16(st + SWZ(row * 128 + sg * 16),
             g_a16 + (size_t)(m0 + row) * H_ + k0 + sg * 8);
    }
    #pragma unroll
    for (int i = 0; i < 4; i++) {          // W: 256 rows x 128B
        int seg = tid + i * 512, row = seg >> 3, sg = seg & 7;
        cp16(st + G_OFF_W + SWZ(row * 128 + sg * 16),
             wL + (size_t)(n0 + row) * H_ + k0 + sg * 8);
    }
}

__global__ __launch_bounds__(512, 1) void gemm_kernel(int layer, int tok0) {
    extern __shared__ __align__(1024) char dsm[];
    uint32_t base = smem_u32(dsm);
    int tid = threadIdx.x, lane = tid & 31, wid = tid >> 5;
    int warp_m = wid & 3, warp_n = wid >> 2;      // 4 x 4 warps
    int n0 = blockIdx.x * 256;
    int m0 = tok0 + blockIdx.y * 128;

    const __half* wL = g_w16 + (size_t)layer * 2 * H_ * H_;

    // per-lane ldmatrix row constants
    int grp = lane >> 3, idx8 = lane & 7;
    int r8 = (grp & 1) * 8 + idx8;
    uint32_t klane = (uint32_t)(grp >> 1) * 16;   // 0 or 16
    uint32_t aoff[2], axor[2], boff[4], bxor[4];
    #pragma unroll
    for (int mt = 0; mt < 2; mt++) {
        int row = warp_m * 32 + mt * 16 + r8;
        aoff[mt] = (uint32_t)row * 128;
        axor[mt] = (uint32_t)(row & 7) << 4;
    }
    #pragma unroll
    for (int nt2 = 0; nt2 < 4; nt2++) {
        int row = warp_n * 64 + nt2 * 16 + r8;
        boff[nt2] = G_OFF_W + (uint32_t)row * 128;
        bxor[nt2] = (uint32_t)(row & 7) << 4;
    }

    float acc[2][8][4];
    #pragma unroll
    for (int mt = 0; mt < 2; mt++)
        #pragma unroll
        for (int nt = 0; nt < 8; nt++)
            #pragma unroll
            for (int u = 0; u < 4; u++) acc[mt][nt][u] = 0.f;

    fetch_chunk(base, 0, m0, n0, wL, tid);
    cp_commit();

    for (int c = 0; c < G_NCHUNK; c++) {
        if (c + 1 < G_NCHUNK) fetch_chunk(base, c + 1, m0, n0, wL, tid);
        cp_commit();
        cp_wait1();                // chunk c resident
        __syncthreads();

        uint32_t stage = base + (uint32_t)(c & 1) * G_STAGE_BYTES;
        #pragma unroll
        for (int ks = 0; ks < 4; ks++) {
            uint32_t kb = (uint32_t)ks * 32 + klane;
            uint32_t a[2][4];
            #pragma unroll
            for (int mt = 0; mt < 2; mt++)
                ldmx4(a[mt], stage + aoff[mt] + (kb ^ axor[mt]));
            uint32_t w[4][4];
            #pragma unroll
            for (int nt2 = 0; nt2 < 4; nt2++)
                ldmx4(w[nt2], stage + boff[nt2] + (kb ^ bxor[nt2]));
            #pragma unroll
            for (int mt = 0; mt < 2; mt++)
                #pragma unroll
                for (int nt2 = 0; nt2 < 4; nt2++) {
                    mma16816(acc[mt][2 * nt2],     a[mt], w[nt2][0], w[nt2][2]);
                    mma16816(acc[mt][2 * nt2 + 1], a[mt], w[nt2][1], w[nt2][3]);
                }
        }
        __syncthreads();           // protect stage (c&1) before fetch (c+2) overwrites
    }

    // epilogue: bias + GLU (adjacent interleaved col pairs in-thread) + residual
    int g = lane >> 2, tig = lane & 3;
    const float* bp = g_biasr + layer * 2 * H_;
    #pragma unroll
    for (int mt = 0; mt < 2; mt++) {
        int mrow = m0 + warp_m * 32 + mt * 16 + g;
        float* hr0 = g_h + (size_t)mrow * H_;
        float* hr1 = hr0 + (size_t)8 * H_;
        #pragma unroll
        for (int nt = 0; nt < 8; nt++) {
            int ncol = n0 + warp_n * 64 + nt * 8 + 2 * tig;  // even
            float b1v = bp[ncol], b2v = bp[ncol + 1];
            int hcol = ncol >> 1;
            float o1 = acc[mt][nt][0] + b1v;
            float o2 = acc[mt][nt][1] + b2v;
            hr0[hcol] += o1 / (1.0f + expf(-o2));
            o1 = acc[mt][nt][2] + b1v;
            o2 = acc[mt][nt][3] + b2v;
            hr1[hcol] += o1 / (1.0f + expf(-o2));
        }
    }
}

// ---------------- launch -------------------------------------------------------------
// R10 stream topology (plain fork, two batch-half chains) — best measured.
extern "C" void kernel_launch(void* const* d_in, const int* in_sizes, int n_in,
                              void* d_out, int out_size) {
    const float* x        = (const float*)d_in[0];
    const float* ln_w     = (const float*)d_in[1];
    const float* ln_b     = (const float*)d_in[2];
    const float* log_dt   = (const float*)d_in[3];
    const float* A_re_log = (const float*)d_in[4];
    const float* A_im     = (const float*)d_in[5];
    const float* C_re     = (const float*)d_in[6];
    const float* C_im     = (const float*)d_in[7];
    const float* D_skip   = (const float*)d_in[8];
    const float* W_out    = (const float*)d_in[9];
    const float* b_out    = (const float*)d_in[10];
    float* out = (float*)d_out;

    static cudaStream_t sA = nullptr, sB = nullptr;
    static cudaEvent_t evRoot = nullptr, evA = nullptr, evB = nullptr;
    if (sA == nullptr) {
        cudaStreamCreateWithFlags(&sA, cudaStreamNonBlocking);
        cudaStreamCreateWithFlags(&sB, cudaStreamNonBlocking);
        cudaEventCreateWithFlags(&evRoot, cudaEventDisableTiming);
        cudaEventCreateWithFlags(&evA, cudaEventDisableTiming);
        cudaEventCreateWithFlags(&evB, cudaEventDisableTiming);
        cudaFuncSetAttribute(gemm_kernel, cudaFuncAttributeMaxDynamicSharedMemorySize,
                             2 * G_STAGE_BYTES);
    }

    int n4 = (TOK_ * H_) / 4;

    // ---- prologue on the capture (default) stream ----
    precompute_kernel<<<(NL_ * H_ * N_ + 255) / 256, 256>>>(log_dt, A_re_log, A_im, C_re, C_im);
    precompute_w_kernel<<<(int)(((size_t)NL_ * 2 * H_ * H_) / 256), 256>>>(W_out, b_out);
    copy_in_kernel<<<n4 / 256, 256>>>((const float4*)x);

    // ---- fork ----
    cudaEventRecord(evRoot, 0);
    cudaStreamWaitEvent(sA, evRoot, 0);
    cudaStreamWaitEvent(sB, evRoot, 0);

    cudaStream_t st[2] = {sA, sB};
    for (int layer = 0; layer < NL_; layer++) {
        for (int c = 0; c < 2; c++) {
            int b0 = c * BH_, tok0 = c * TOKH_, bh0 = b0 * H_;
            cudaStream_t s = st[c];
            ln_stats_kernel<<<TOKH_ / 8, 256, 0, s>>>(tok0);
            ln_apply_t_kernel<<<dim3(H_ / 32, L_ / 32, BH_), dim3(32, 8), 0, s>>>(
                ln_w, ln_b, layer, b0);
            scan_kernel<<<(BH_ * H_) / 8, 256, 0, s>>>(D_skip, layer, bh0);
            convert_kernel<<<dim3(H_ / 32, L_ / 32, BH_), dim3(32, 8), 0, s>>>(b0);
            gemm_kernel<<<dim3(2 * H_ / 256, TOKH_ / 128), 512, 2 * G_STAGE_BYTES, s>>>(
                layer, tok0);
        }
    }

    // ---- join ----
    cudaEventRecord(evA, sA);
    cudaEventRecord(evB, sB);
    cudaStreamWaitEvent(0, evA, 0);
    cudaStreamWaitEvent(0, evB, 0);

    copy_out_kernel<<<n4 / 256, 256>>>((float4*)out);
}